// round 1
// baseline (speedup 1.0000x reference)
#include <cuda_runtime.h>
#include <cuda_bf16.h>
#include <math.h>

// Problem constants
#define B_   512
#define T_   128
#define F_   256
#define H_   384
#define L_   3
#define K_   10
#define LAB_ 25
#define G_   1542   // 4*H + 2*L
#define CH_  128    // H / L

typedef unsigned long long ull;

// ---------------- scratch (device globals; no allocations allowed) ----------
__device__ float g_XO[(size_t)T_ * B_ * G_];    // precomputed input projection [t][b][g]
__device__ float g_U[B_ * G_];                  // per-step gate pre-activations
__device__ float g_h[B_ * H_];
__device__ float g_c[B_ * H_];
__device__ float g_Hall[(size_t)T_ * B_ * H_];  // h history [t][b][h]
__device__ float g_D[T_ * B_];                  // cur_dist history [t][b]
__device__ float g_LH[B_ * H_ * K_];            // local_h at t* [b][h*K+k]
__device__ float g_TH2[B_ * H_];                // theme after MLP at t*
__device__ float g_RNN[B_ * H_];                // theme*conv + h at t*

// ---------------- f32x2 helpers (Blackwell packed fp32 pipe) -----------------
__device__ __forceinline__ ull pack2(float lo, float hi) {
    ull r;
    asm("mov.b64 %0, {%1, %2};" : "=l"(r) : "f"(lo), "f"(hi));
    return r;
}
__device__ __forceinline__ ull fma2(ull a, ull b, ull c) {
    ull d;
    asm("fma.rn.f32x2 %0, %1, %2, %3;" : "=l"(d) : "l"(a), "l"(b), "l"(c));
    return d;
}
__device__ __forceinline__ float2 unpack2(ull v) {
    float2 f;
    asm("mov.b64 {%0, %1}, %2;" : "=f"(f.x), "=f"(f.y) : "l"(v));
    return f;
}
__device__ __forceinline__ float sigmoidf_(float x) {
    return 1.0f / (1.0f + expf(-x));
}

// ---------------- zero h/c state ---------------------------------------------
__global__ void k_zero() {
    int i = blockIdx.x * blockDim.x + threadIdx.x;
    if (i < B_ * H_) { g_h[i] = 0.0f; g_c[i] = 0.0f; }
}

// ---------------- precompute GEMM --------------------------------------------
// XO[m=t*512+b][n] = sum_f X[b,t,f]*KW[f,n] + KB[n] + RB[n] + (t>0)*(KW[F,n]+RW[H,n])
// BM=128, BN=64, BK=32, 256 threads, thread tile 8x4 (2 f32x2 cols)
__global__ __launch_bounds__(256) void k_pre(
    const float* __restrict__ X, const float* __restrict__ KW,
    const float* __restrict__ KB, const float* __restrict__ RW,
    const float* __restrict__ RB)
{
    __shared__ float As[32][129];
    __shared__ float Bs[32][64];
    const int tid = threadIdx.x;
    const int tx = tid & 15, ty = tid >> 4;
    const int n0 = blockIdx.x * 64;
    const int m0 = blockIdx.y * 128;

    ull acc[8][2];
#pragma unroll
    for (int i = 0; i < 8; ++i) { acc[i][0] = 0ull; acc[i][1] = 0ull; }

    for (int k0 = 0; k0 < F_; k0 += 32) {
#pragma unroll
        for (int i = 0; i < 16; ++i) {
            int li = i * 256 + tid;
            int kk = li & 31, r = li >> 5;
            int m = m0 + r;
            int b = m & 511, t = m >> 9;
            As[kk][r] = X[(b * T_ + t) * F_ + k0 + kk];
        }
#pragma unroll
        for (int i = 0; i < 8; ++i) {
            int li = i * 256 + tid;
            int n = li & 63, kk = li >> 6;
            int gn = n0 + n;
            Bs[kk][n] = (gn < G_) ? KW[(k0 + kk) * G_ + gn] : 0.0f;
        }
        __syncthreads();
#pragma unroll
        for (int kk = 0; kk < 32; ++kk) {
            ull b0 = *(const ull*)&Bs[kk][tx * 4];
            ull b1 = *(const ull*)&Bs[kk][tx * 4 + 2];
#pragma unroll
            for (int i = 0; i < 8; ++i) {
                float a = As[kk][ty * 8 + i];
                ull av = pack2(a, a);
                acc[i][0] = fma2(av, b0, acc[i][0]);
                acc[i][1] = fma2(av, b1, acc[i][1]);
            }
        }
        __syncthreads();
    }
#pragma unroll
    for (int i = 0; i < 8; ++i) {
        int m = m0 + ty * 8 + i;
        int t = m >> 9;
        float tb = (t > 0) ? 1.0f : 0.0f;
#pragma unroll
        for (int j = 0; j < 2; ++j) {
            int n = n0 + tx * 4 + j * 2;
            float2 v = unpack2(acc[i][j]);
            if (n < G_) {
                float bias = KB[n] + RB[n] + tb * (KW[F_ * G_ + n] + RW[H_ * G_ + n]);
                g_XO[(size_t)m * G_ + n] = v.x + bias;
            }
            if (n + 1 < G_) {
                float bias = KB[n + 1] + RB[n + 1] + tb * (KW[F_ * G_ + n + 1] + RW[H_ * G_ + n + 1]);
                g_XO[(size_t)m * G_ + n + 1] = v.y + bias;
            }
        }
    }
}

// ---------------- per-step recurrent GEMM ------------------------------------
// U[b][n] = XO[t][b][n] + sum_j h[b,j]*RW[j,n]
// BM=32, BN=64, BK=32, 256 threads, thread tile 2x4
__global__ __launch_bounds__(256) void k_step_gemm(int t, const float* __restrict__ RW)
{
    __shared__ float As[32][33];
    __shared__ float Bs[32][64];
    const int tid = threadIdx.x;
    const int tx = tid & 15, ty = tid >> 4;
    const int n0 = blockIdx.x * 64;
    const int m0 = blockIdx.y * 32;

    ull acc[2][2];
    acc[0][0] = acc[0][1] = acc[1][0] = acc[1][1] = 0ull;

    for (int k0 = 0; k0 < H_; k0 += 32) {
#pragma unroll
        for (int i = 0; i < 4; ++i) {
            int li = i * 256 + tid;
            int kk = li & 31, r = li >> 5;
            As[kk][r] = g_h[(m0 + r) * H_ + k0 + kk];
        }
#pragma unroll
        for (int i = 0; i < 8; ++i) {
            int li = i * 256 + tid;
            int n = li & 63, kk = li >> 6;
            int gn = n0 + n;
            Bs[kk][n] = (gn < G_) ? RW[(k0 + kk) * G_ + gn] : 0.0f;
        }
        __syncthreads();
#pragma unroll
        for (int kk = 0; kk < 32; ++kk) {
            ull b0 = *(const ull*)&Bs[kk][tx * 4];
            ull b1 = *(const ull*)&Bs[kk][tx * 4 + 2];
#pragma unroll
            for (int i = 0; i < 2; ++i) {
                float a = As[kk][ty * 2 + i];
                ull av = pack2(a, a);
                acc[i][0] = fma2(av, b0, acc[i][0]);
                acc[i][1] = fma2(av, b1, acc[i][1]);
            }
        }
        __syncthreads();
    }
    const size_t xo_base = (size_t)(t * B_) * G_;
#pragma unroll
    for (int i = 0; i < 2; ++i) {
        int b = m0 + ty * 2 + i;
#pragma unroll
        for (int j = 0; j < 2; ++j) {
            int n = n0 + tx * 4 + j * 2;
            float2 v = unpack2(acc[i][j]);
            if (n < G_)     g_U[b * G_ + n]     = v.x + g_XO[xo_base + (size_t)b * G_ + n];
            if (n + 1 < G_) g_U[b * G_ + n + 1] = v.y + g_XO[xo_base + (size_t)b * G_ + n + 1];
        }
    }
}

// ---------------- per-step gates / state update ------------------------------
__global__ __launch_bounds__(128) void k_step_elem(int t)
{
    const int b = blockIdx.x;
    const int ch = threadIdx.x;  // 0..127
    __shared__ float fm_s[3], im_s[3];

    if (ch == 0) {
        // fm = cumsum_l2r(softmax(U[b,0:3]))
        float f0 = g_U[b * G_ + 0], f1 = g_U[b * G_ + 1], f2 = g_U[b * G_ + 2];
        float mx = fmaxf(f0, fmaxf(f1, f2));
        float e0 = expf(f0 - mx), e1 = expf(f1 - mx), e2 = expf(f2 - mx);
        float inv = 1.0f / (e0 + e1 + e2);
        float s0 = e0 * inv, s1 = e1 * inv, s2 = e2 * inv;
        float fm0 = s0, fm1 = s0 + s1, fm2 = s0 + s1 + s2;
        fm_s[0] = fm0; fm_s[1] = fm1; fm_s[2] = fm2;
        // im = cumsum_r2l(softmax(U[b,3:6]))
        float g0 = g_U[b * G_ + 3], g1 = g_U[b * G_ + 4], g2 = g_U[b * G_ + 5];
        float mx2 = fmaxf(g0, fmaxf(g1, g2));
        float q0 = expf(g0 - mx2), q1 = expf(g1 - mx2), q2 = expf(g2 - mx2);
        float inv2 = 1.0f / (q0 + q1 + q2);
        float t0 = q0 * inv2, t1 = q1 * inv2, t2 = q2 * inv2;
        im_s[2] = t2; im_s[1] = t1 + t2; im_s[0] = t0 + t1 + t2;
        g_D[t * B_ + b] = 1.0f - (fm0 + fm1 + fm2) * (1.0f / 3.0f);
    }
    __syncthreads();

    const float* Ub = g_U + b * G_ + 2 * L_;
#pragma unroll
    for (int l = 0; l < 3; ++l) {
        float fg = sigmoidf_(Ub[(0 + l) * CH_ + ch]);
        float ig = sigmoidf_(Ub[(3 + l) * CH_ + ch]);
        float og = sigmoidf_(Ub[(6 + l) * CH_ + ch]);
        float ci = tanhf(Ub[(9 + l) * CH_ + ch]);
        int hidx = b * H_ + l * CH_ + ch;
        float c = g_c[hidx];
        float fmv = fm_s[l], imv = im_s[l], ov = fmv * imv;
        float cn = ov * (fg * c + ig * ci) + (fmv - ov) * c + (imv - ov) * ci;
        float hn = og * tanhf(cn);
        g_c[hidx] = cn;
        g_h[hidx] = hn;
        g_Hall[(size_t)(t * B_ + b) * H_ + l * CH_ + ch] = hn;
    }
}

// ---------------- finale A: window gather, local_dis, theme MLP --------------
__global__ __launch_bounds__(384) void k_final_a(
    const int* __restrict__ vlen,
    const float* __restrict__ SW, const float* __restrict__ SB,
    const float* __restrict__ RSW, const float* __restrict__ RSB)
{
    const int b = blockIdx.x;
    const int tid = threadIdx.x;  // 0..383
    __shared__ float ld[K_];
    __shared__ float theme_s[H_];
    __shared__ float mid_s[64];

    int tstar = vlen[b] - 1;
    if (tstar < 0) tstar = 0;
    if (tstar > T_ - 1) tstar = T_ - 1;

    if (tid == 0) {
        float cs = 0.0f, mx = -1e30f;
        float csv[K_];
#pragma unroll
        for (int k = 0; k < K_; ++k) {
            int tw = tstar - (K_ - 1) + k;
            float d = (tw >= 0) ? g_D[tw * B_ + b] : 0.0f;
            cs += d;
            csv[k] = cs;
            mx = fmaxf(mx, cs);
        }
        float sum = 0.0f;
#pragma unroll
        for (int k = 0; k < K_; ++k) { csv[k] = expf(csv[k] - mx); sum += csv[k]; }
        float inv = 1.0f / sum;
#pragma unroll
        for (int k = 0; k < K_; ++k) ld[k] = csv[k] * inv;
    }
    __syncthreads();

    float th = 0.0f;
    float lh[K_];
#pragma unroll
    for (int k = 0; k < K_; ++k) {
        int tw = tstar - (K_ - 1) + k;
        float hv = (tw >= 0) ? g_Hall[(size_t)(tw * B_ + b) * H_ + tid] : 0.0f;
        float v = hv * ld[k];
        lh[k] = v;
        th += v;
    }
    th *= (1.0f / (float)K_);
#pragma unroll
    for (int k = 0; k < K_; ++k) g_LH[(size_t)b * (H_ * K_) + tid * K_ + k] = lh[k];
    theme_s[tid] = th;
    __syncthreads();

    if (tid < 64) {
        float acc = SB[tid];
        for (int h = 0; h < H_; ++h) acc += theme_s[h] * SW[h * 64 + tid];
        mid_s[tid] = fmaxf(acc, 0.0f);
    }
    __syncthreads();
    {
        float acc = RSB[tid];
#pragma unroll
        for (int j = 0; j < 64; ++j) acc += mid_s[j] * RSW[j * H_ + tid];
        g_TH2[b * H_ + tid] = sigmoidf_(acc);
    }
}

// ---------------- finale B: conv as GEMM + combine ---------------------------
// conv[b,o] = sum_x LH[b,x]*CW[o,x];  RNN[b,o] = TH2[b,o]*(conv+CB[o]) + h(t*)[b,o]
// BM=64 (b), BN=32 (o), BK=32, 256 threads, thread tile 4x2
__global__ __launch_bounds__(256) void k_final_conv(
    const float* __restrict__ CW, const float* __restrict__ CB,
    const int* __restrict__ vlen)
{
    __shared__ float As[32][65];
    __shared__ float Bs[32][34];
    const int tid = threadIdx.x;
    const int tx = tid & 15, ty = tid >> 4;
    const int n0 = blockIdx.x * 32;
    const int m0 = blockIdx.y * 64;
    const int XK = H_ * K_;  // 3840

    ull acc[4];
    acc[0] = acc[1] = acc[2] = acc[3] = 0ull;

    for (int x0 = 0; x0 < XK; x0 += 32) {
#pragma unroll
        for (int i = 0; i < 8; ++i) {
            int li = i * 256 + tid;
            int kk = li & 31, r = li >> 5;
            As[kk][r] = g_LH[(size_t)(m0 + r) * XK + x0 + kk];
        }
#pragma unroll
        for (int i = 0; i < 4; ++i) {
            int li = i * 256 + tid;
            int kk = li & 31, n = li >> 5;
            Bs[kk][n] = CW[(size_t)(n0 + n) * XK + x0 + kk];
        }
        __syncthreads();
#pragma unroll
        for (int kk = 0; kk < 32; ++kk) {
            ull b0 = *(const ull*)&Bs[kk][tx * 2];
#pragma unroll
            for (int i = 0; i < 4; ++i) {
                float a = As[kk][ty * 4 + i];
                acc[i] = fma2(pack2(a, a), b0, acc[i]);
            }
        }
        __syncthreads();
    }
#pragma unroll
    for (int i = 0; i < 4; ++i) {
        int b = m0 + ty * 4 + i;
        int tstar = vlen[b] - 1;
        if (tstar < 0) tstar = 0;
        if (tstar > T_ - 1) tstar = T_ - 1;
        int n = n0 + tx * 2;
        float2 v = unpack2(acc[i]);
        float c0 = v.x + CB[n];
        float c1 = v.y + CB[n + 1];
        const size_t hb = (size_t)(tstar * B_ + b) * H_;
        g_RNN[b * H_ + n]     = g_TH2[b * H_ + n]     * c0 + g_Hall[hb + n];
        g_RNN[b * H_ + n + 1] = g_TH2[b * H_ + n + 1] * c1 + g_Hall[hb + n + 1];
    }
}

// ---------------- finale C: output projection --------------------------------
__global__ __launch_bounds__(32) void k_final_out(
    const float* __restrict__ OW, const float* __restrict__ OB,
    float* __restrict__ out)
{
    const int b = blockIdx.x;
    const int tid = threadIdx.x;  // 0..31
    __shared__ float r_s[H_];
    for (int i = tid; i < H_; i += 32) r_s[i] = g_RNN[b * H_ + i];
    __syncwarp();
    if (tid < LAB_) {
        float acc = OB[tid];
        for (int h = 0; h < H_; ++h) acc += r_s[h] * OW[h * LAB_ + tid];
        out[b * LAB_ + tid] = acc;
    }
}

// ---------------- launcher ---------------------------------------------------
extern "C" void kernel_launch(void* const* d_in, const int* in_sizes, int n_in,
                              void* d_out, int out_size)
{
    const float* X    = (const float*)d_in[0];
    const int*   vlen = (const int*)  d_in[1];
    const float* KW   = (const float*)d_in[2];
    const float* KB   = (const float*)d_in[3];
    const float* RW   = (const float*)d_in[4];
    const float* RB   = (const float*)d_in[5];
    const float* SW   = (const float*)d_in[6];
    const float* SB   = (const float*)d_in[7];
    const float* RSW  = (const float*)d_in[8];
    const float* RSB  = (const float*)d_in[9];
    const float* CW   = (const float*)d_in[10];
    const float* CB   = (const float*)d_in[11];
    const float* OW   = (const float*)d_in[12];
    const float* OB   = (const float*)d_in[13];
    float* out = (float*)d_out;

    k_zero<<<(B_ * H_ + 255) / 256, 256>>>();
    k_pre<<<dim3((G_ + 63) / 64, (T_ * B_) / 128), 256>>>(X, KW, KB, RW, RB);

    for (int t = 0; t < T_; ++t) {
        k_step_gemm<<<dim3((G_ + 63) / 64, B_ / 32), 256>>>(t, RW);
        k_step_elem<<<B_, CH_>>>(t);
    }

    k_final_a<<<B_, H_>>>(vlen, SW, SB, RSW, RSB);
    k_final_conv<<<dim3(H_ / 32, B_ / 64), 256>>>(CW, CB, vlen);
    k_final_out<<<B_, 32>>>(OW, OB, out);
}